// round 15
// baseline (speedup 1.0000x reference)
#include <cuda_runtime.h>
#include <cstdint>

// YOLOv1 loss — single fused kernel.
// R15 = R14 resubmit (infra flake last round): TMA-bulk producer/consumer
// pipeline. Thread 96 issues cp.async.bulk (2 per tile) into a 4-stage
// mbarrier ring; warps 0-1 (64 threads) compute one cell each per tile
// directly from smem. Zero LDGSTS in the hot loop.

#define TPB   128
#define TILE  64
#define TEN_B (TILE * 30 * 4)             // 7680 B per tensor per stage
#define STAGE_BYTES (2 * TEN_B)           // 15360 B (pred + target)
#define NSTAGE 4
#define SMEM_BYTES (NSTAGE * STAGE_BYTES) // 61440 B -> 3 CTAs/SM
#define NCONS 64                          // consumer threads (warps 0-1)
#define GRID_MAX 1024

__device__ float g_partials[GRID_MAX * 5];
__device__ unsigned int g_ticket = 0;

__device__ __forceinline__ uint32_t smem_u32(const void* p) {
    uint32_t a;
    asm("{ .reg .u64 t; cvta.to.shared.u64 t, %1; cvt.u32.u64 %0, t; }"
        : "=r"(a) : "l"(p));
    return a;
}
__device__ __forceinline__ void mbar_init(uint32_t mbar, uint32_t cnt) {
    asm volatile("mbarrier.init.shared.b64 [%0], %1;" :: "r"(mbar), "r"(cnt) : "memory");
}
__device__ __forceinline__ void mbar_expect_tx(uint32_t mbar, uint32_t bytes) {
    asm volatile("mbarrier.arrive.expect_tx.shared.b64 _, [%0], %1;"
                 :: "r"(mbar), "r"(bytes) : "memory");
}
__device__ __forceinline__ void mbar_arrive(uint32_t mbar) {
    asm volatile("mbarrier.arrive.shared.b64 _, [%0];" :: "r"(mbar) : "memory");
}
__device__ __forceinline__ void mbar_wait(uint32_t mbar, uint32_t parity) {
    uint32_t done;
    asm volatile(
        "{\n\t.reg .pred p;\n\t"
        "mbarrier.try_wait.parity.acquire.cta.shared::cta.b64 p, [%1], %2;\n\t"
        "selp.b32 %0, 1, 0, p;\n\t}"
        : "=r"(done) : "r"(mbar), "r"(parity) : "memory");
    if (!done) {
        asm volatile(
            "{\n\t.reg .pred P1;\n\t"
            "W_%=:\n\t"
            "mbarrier.try_wait.parity.acquire.cta.shared::cta.b64 P1, [%0], %1, 0x989680;\n\t"
            "@P1 bra.uni D_%=;\n\t"
            "bra.uni W_%=;\n\t"
            "D_%=:\n\t}"
            :: "r"(mbar), "r"(parity) : "memory");
    }
}
__device__ __forceinline__ void bulk_g2s(uint32_t sdst, const void* gsrc,
                                         uint32_t bytes, uint32_t mbar) {
    asm volatile(
        "cp.async.bulk.shared::cluster.global.mbarrier::complete_tx::bytes "
        "[%0], [%1], %2, [%3];"
        :: "r"(sdst), "l"(gsrc), "r"(bytes), "r"(mbar) : "memory");
}

__device__ __forceinline__ float iou_fn(float bx, float by, float bw, float bh,
                                        float tx, float ty, float tw, float th)
{
    float ax1 = bx - bw * 0.5f, ay1 = by - bh * 0.5f;
    float ax2 = bx + bw * 0.5f, ay2 = by + bh * 0.5f;
    float cx1 = tx - tw * 0.5f, cy1 = ty - th * 0.5f;
    float cx2 = tx + tw * 0.5f, cy2 = ty + th * 0.5f;
    float iw = fmaxf(fminf(ax2, cx2) - fmaxf(ax1, cx1), 0.0f);
    float ih = fmaxf(fminf(ay2, cy2) - fmaxf(ay1, cy1), 0.0f);
    float inter = iw * ih;
    float uni = bw * bh + tw * th - inter;
    return inter / fmaxf(uni, 1e-10f);
}

// Direct-memory per-cell update (no register arrays -> no local spills).
__device__ __forceinline__ void cell_update(const float* P, const float* T,
                                            float& a0, float& a1, float& a2,
                                            float& a3, float& a4)
{
    float t4v  = T[4];
    float objf = (t4v == 1.0f) ? 1.0f : 0.0f;
    float noobjf = 1.0f - objf;

    float tx = T[0], ty = T[1], tw = T[2], th = T[3];
    float i0 = iou_fn(P[0], P[1], P[2], P[3], tx, ty, tw, th);
    float i1 = iou_fn(P[5], P[6], P[7], P[8], tx, ty, tw, th);

    bool b0 = (i0 > i1);   // ties -> box 1 (matches jnp.where)
    float wx = b0 ? P[0] : P[5];
    float wy = b0 ? P[1] : P[6];
    float ww = b0 ? P[2] : P[7];
    float wh = b0 ? P[3] : P[8];
    float wc = b0 ? P[4] : P[9];
    float wiou = fmaxf(i0, i1);

    float dx = wx - tx, dy = wy - ty;
    float dw = sqrtf(ww) - sqrtf(tw);
    float dh = sqrtf(wh) - sqrtf(th);
    a0 += (dx * dx + dy * dy + dw * dw + dh * dh) * objf;

    float dc = wc - wiou;
    a1 += dc * dc * objf;

    float d4 = P[4] - t4v;
    float d9 = P[9] - T[9];
    a2 += (d4 * d4 + d9 * d9) * noobjf;

    float m = -1e30f;
    #pragma unroll
    for (int c = 0; c < 20; c++) m = fmaxf(m, P[10 + c]);
    float sum = 0.0f;
    #pragma unroll
    for (int c = 0; c < 20; c++) sum += __expf(P[10 + c] - m);
    float tm = -1e30f; int targc = 0;
    #pragma unroll
    for (int c = 0; c < 20; c++) {
        float v = T[10 + c];
        if (v > tm) { tm = v; targc = c; }   // first-occurrence argmax
    }
    float ce = m + __logf(sum) - P[10 + targc];
    a3 += ce * objf;
    a4 += objf;
}

extern __shared__ char dynbuf[];   // NSTAGE x STAGE_BYTES

__global__ __launch_bounds__(TPB)
void yolo_fused_kernel(const float* __restrict__ pred,
                       const float* __restrict__ target,
                       int n_cells, float invB,
                       float* __restrict__ out)
{
    const int tid = threadIdx.x;
    const int nb  = gridDim.x;
    const long long ntiles = n_cells / TILE;
    const int rem = n_cells - (int)(ntiles * TILE);

    __shared__ unsigned long long mb_full[NSTAGE];
    __shared__ unsigned long long mb_empty[NSTAGE];
    __shared__ float sred[5][TPB / 32];
    __shared__ int amLast;

    const uint32_t mbf = smem_u32(&mb_full[0]);
    const uint32_t mbe = smem_u32(&mb_empty[0]);
    const uint32_t sbase = smem_u32(dynbuf);

    if (tid == 0) {
        #pragma unroll
        for (int s = 0; s < NSTAGE; s++) {
            mbar_init(mbf + 8u * s, 1);       // completed by expect_tx + bytes
            mbar_init(mbe + 8u * s, NCONS);   // consumers arrive after reading
        }
        asm volatile("fence.proxy.async.shared::cta;" ::: "memory");
    }
    __syncthreads();

    float acc0 = 0.f, acc1 = 0.f, acc2 = 0.f, acc3 = 0.f, acc4 = 0.f;

    // Remainder cells: block 0 handles directly from global (tiny).
    if (rem && blockIdx.x == 0 && tid < rem) {
        long long c0 = ntiles * TILE + tid;
        cell_update(pred + c0 * 30, target + c0 * 30,
                    acc0, acc1, acc2, acc3, acc4);
    }

    const long long t0 = blockIdx.x;
    long long niter = 0;
    if (t0 < ntiles) niter = (ntiles - t0 + nb - 1) / nb;

    if (tid == 96) {
        // ---- producer: single thread, backpressured by empty barriers.
        // Phase starts at 1 so the first NSTAGE empty-waits pass immediately
        // (ptx_helpers Pipeline convention: producer_flip_phase).
        int s = 0; uint32_t ephase = 1;
        for (long long it = 0; it < niter; ++it) {
            mbar_wait(mbe + 8u * s, ephase);
            long long t = t0 + it * nb;
            uint32_t dst = sbase + (uint32_t)s * STAGE_BYTES;
            mbar_expect_tx(mbf + 8u * s, STAGE_BYTES);
            bulk_g2s(dst,                   pred   + t * (TILE * 30), TEN_B, mbf + 8u * s);
            bulk_g2s(dst + (uint32_t)TEN_B, target + t * (TILE * 30), TEN_B, mbf + 8u * s);
            if (++s == NSTAGE) { s = 0; ephase ^= 1; }
        }
    } else if (tid < NCONS) {
        // ---- consumers: warps 0-1, one cell per tile each ----
        int s = 0; uint32_t fphase = 0;
        for (long long it = 0; it < niter; ++it) {
            mbar_wait(mbf + 8u * s, fphase);
            const float* sp = (const float*)(dynbuf + (size_t)s * STAGE_BYTES);
            const float* P = sp + tid * 30;
            const float* T = sp + (TEN_B / 4) + tid * 30;
            cell_update(P, T, acc0, acc1, acc2, acc3, acc4);
            mbar_arrive(mbe + 8u * s);
            if (++s == NSTAGE) { s = 0; fphase ^= 1; }
        }
    }

    // ---- deterministic in-block reduction (all 128 threads) ----
    const unsigned mask = 0xffffffffu;
    #pragma unroll
    for (int off = 16; off; off >>= 1) {
        acc0 += __shfl_down_sync(mask, acc0, off);
        acc1 += __shfl_down_sync(mask, acc1, off);
        acc2 += __shfl_down_sync(mask, acc2, off);
        acc3 += __shfl_down_sync(mask, acc3, off);
        acc4 += __shfl_down_sync(mask, acc4, off);
    }
    int lane = tid & 31, w = tid >> 5;
    if (lane == 0) {
        sred[0][w] = acc0; sred[1][w] = acc1; sred[2][w] = acc2;
        sred[3][w] = acc3; sred[4][w] = acc4;
    }
    __syncthreads();
    if (tid == 0) {
        float r0 = 0.f, r1 = 0.f, r2 = 0.f, r3 = 0.f, r4 = 0.f;
        #pragma unroll
        for (int i = 0; i < TPB / 32; i++) {
            r0 += sred[0][i]; r1 += sred[1][i]; r2 += sred[2][i];
            r3 += sred[3][i]; r4 += sred[4][i];
        }
        g_partials[blockIdx.x * 5 + 0] = r0;
        g_partials[blockIdx.x * 5 + 1] = r1;
        g_partials[blockIdx.x * 5 + 2] = r2;
        g_partials[blockIdx.x * 5 + 3] = r3;
        g_partials[blockIdx.x * 5 + 4] = r4;
    }

    // ---- ticket: last finishing block finalizes ----
    __threadfence();
    __syncthreads();
    if (tid == 0) {
        unsigned tk = atomicAdd(&g_ticket, 1u);
        amLast = (tk == (unsigned)(nb - 1));
    }
    __syncthreads();

    if (amLast) {
        float a0 = 0.f, a1 = 0.f, a2 = 0.f, a3 = 0.f, a4 = 0.f;
        for (int j = tid; j < nb; j += TPB) {
            a0 += g_partials[j * 5 + 0];
            a1 += g_partials[j * 5 + 1];
            a2 += g_partials[j * 5 + 2];
            a3 += g_partials[j * 5 + 3];
            a4 += g_partials[j * 5 + 4];
        }
        #pragma unroll
        for (int off = 16; off; off >>= 1) {
            a0 += __shfl_down_sync(mask, a0, off);
            a1 += __shfl_down_sync(mask, a1, off);
            a2 += __shfl_down_sync(mask, a2, off);
            a3 += __shfl_down_sync(mask, a3, off);
            a4 += __shfl_down_sync(mask, a4, off);
        }
        if (lane == 0) {
            sred[0][w] = a0; sred[1][w] = a1; sred[2][w] = a2;
            sred[3][w] = a3; sred[4][w] = a4;
        }
        __syncthreads();
        if (tid == 0) {
            float loc = 0.f, cobj = 0.f, cno = 0.f, ce = 0.f, nobj = 0.f;
            #pragma unroll
            for (int i = 0; i < TPB / 32; i++) {
                loc += sred[0][i]; cobj += sred[1][i]; cno += sred[2][i];
                ce  += sred[3][i]; nobj += sred[4][i];
            }
            float n   = fmaxf(nobj, 1.0f);
            float cls = ce / n;
            out[0] = (5.0f * loc + cobj + 0.5f * cno + cls) * invB;
            out[1] = loc;
            out[2] = cobj;
            out[3] = cno;
            out[4] = cls;
            __threadfence();
            g_ticket = 0;   // reset for next graph replay
        }
    }
}

extern "C" void kernel_launch(void* const* d_in, const int* in_sizes, int n_in,
                              void* d_out, int out_size)
{
    const float* pred   = (const float*)d_in[0];
    const float* target = (const float*)d_in[1];
    int n_elems = in_sizes[0];
    int n_cells = n_elems / 30;

    static bool configured = false;
    if (!configured) {
        cudaFuncSetAttribute(yolo_fused_kernel,
                             cudaFuncAttributeMaxDynamicSharedMemorySize,
                             SMEM_BYTES);
        configured = true;
    }

    long long ntiles = n_cells / TILE;
    int grid = 444;                        // 148 SMs x 3 CTAs @ 61.4 KB smem
    if (ntiles >= 1 && grid > ntiles) grid = (int)ntiles;
    if (grid < 1) grid = 1;
    if (grid > GRID_MAX) grid = GRID_MAX;

    float invB = 49.0f / (float)n_cells;   // B = n_cells / 49

    yolo_fused_kernel<<<grid, TPB, SMEM_BYTES>>>(pred, target, n_cells, invB,
                                                 (float*)d_out);
}

// round 16
// speedup vs baseline: 1.0526x; 1.0526x over previous
#include <cuda_runtime.h>
#include <cstdint>

// YOLOv1 loss — single fused kernel, cp.async 2-stage pipeline, ticket finalize.
// FINAL: exact reproduction of the round-2 winner (38.8 us, ~97% of the
// empirically measured ~5.15 TB/s streaming roofline for this kernel).
// pred/target: (B, 7, 7, 30) fp32; out: 5 fp32 scalars.

#define TPB   128
#define TILE  128
#define NF4   (TILE * 30 / 4)          // 960 float4 per tensor per tile
#define STAGE_BYTES (2 * NF4 * 16)     // pred+target, one stage = 30720 B
#define SMEM_BYTES  (2 * STAGE_BYTES)  // 2 stages = 61440 B
#define GRID_MAX 1024

__device__ float g_partials[GRID_MAX * 5];
__device__ unsigned int g_ticket = 0;

__device__ __forceinline__ void cp16(unsigned dst, const void* src) {
    asm volatile("cp.async.cg.shared.global [%0], [%1], 16;" :: "r"(dst), "l"(src));
}

__device__ __forceinline__ float iou_fn(float bx, float by, float bw, float bh,
                                        float tx, float ty, float tw, float th)
{
    float ax1 = bx - bw * 0.5f, ay1 = by - bh * 0.5f;
    float ax2 = bx + bw * 0.5f, ay2 = by + bh * 0.5f;
    float cx1 = tx - tw * 0.5f, cy1 = ty - th * 0.5f;
    float cx2 = tx + tw * 0.5f, cy2 = ty + th * 0.5f;
    float iw = fmaxf(fminf(ax2, cx2) - fmaxf(ax1, cx1), 0.0f);
    float ih = fmaxf(fminf(ay2, cy2) - fmaxf(ay1, cy1), 0.0f);
    float inter = iw * ih;
    float uni = bw * bh + tw * th - inter;
    return inter / fmaxf(uni, 1e-10f);
}

extern __shared__ float4 dynbuf[];   // [2 stages][2 tensors][NF4]

__global__ __launch_bounds__(TPB)
void yolo_fused_kernel(const float* __restrict__ pred,
                       const float* __restrict__ target,
                       int n_cells, float invB,
                       float* __restrict__ out)
{
    const int tid = threadIdx.x;
    const int nb  = gridDim.x;
    const int ntiles = (n_cells + TILE - 1) / TILE;

    float acc0 = 0.f, acc1 = 0.f, acc2 = 0.f, acc3 = 0.f, acc4 = 0.f;

    // ---- issue loads for one tile into stage s (one commit_group per call) ----
    auto issue = [&](int tile, int s) {
        long long c0 = (long long)tile * TILE;
        int valid = (int)min((long long)TILE, (long long)n_cells - c0);
        const float* pg = pred   + c0 * 30;
        const float* tg = target + c0 * 30;
        float* sp = (float*)(dynbuf + (size_t)s * 2 * NF4);
        float* st = sp + NF4 * 4;
        if (valid == TILE) {
            unsigned bp = (unsigned)__cvta_generic_to_shared(sp);
            unsigned bt = (unsigned)__cvta_generic_to_shared(st);
            #pragma unroll 4
            for (int i = tid; i < NF4; i += TPB) {
                cp16(bp + 16u * i, ((const float4*)pg) + i);
                cp16(bt + 16u * i, ((const float4*)tg) + i);
            }
        } else {
            for (int i = tid; i < valid * 30; i += TPB) {
                sp[i] = pg[i];
                st[i] = tg[i];
            }
        }
        asm volatile("cp.async.commit_group;");
    };

    int t = blockIdx.x;
    if (t < ntiles) issue(t, 0);

    int s = 0;
    for (; t < ntiles; t += nb, s ^= 1) {
        long long c0 = (long long)t * TILE;
        int valid = (int)min((long long)TILE, (long long)n_cells - c0);

        int tn = t + nb;
        if (tn < ntiles) {
            issue(tn, s ^ 1);
            asm volatile("cp.async.wait_group 1;");
        } else {
            asm volatile("cp.async.wait_group 0;");
        }
        __syncthreads();

        if (tid < valid) {
            const float* sp = (const float*)(dynbuf + (size_t)s * 2 * NF4);
            const float* P = sp + tid * 30;
            const float* T = sp + NF4 * 4 + tid * 30;

            float t4v  = T[4];
            float objf = (t4v == 1.0f) ? 1.0f : 0.0f;
            float noobjf = 1.0f - objf;

            float tx = T[0], ty = T[1], tw = T[2], th = T[3];
            float i0 = iou_fn(P[0], P[1], P[2], P[3], tx, ty, tw, th);
            float i1 = iou_fn(P[5], P[6], P[7], P[8], tx, ty, tw, th);

            bool b0 = (i0 > i1);   // ties -> box 1 (matches jnp.where)
            float wx = b0 ? P[0] : P[5];
            float wy = b0 ? P[1] : P[6];
            float ww = b0 ? P[2] : P[7];
            float wh = b0 ? P[3] : P[8];
            float wc = b0 ? P[4] : P[9];
            float wiou = fmaxf(i0, i1);

            float dx = wx - tx, dy = wy - ty;
            float dw = sqrtf(ww) - sqrtf(tw);
            float dh = sqrtf(wh) - sqrtf(th);
            acc0 += (dx * dx + dy * dy + dw * dw + dh * dh) * objf;

            float dc = wc - wiou;
            acc1 += dc * dc * objf;

            float d4 = P[4] - t4v;
            float d9 = P[9] - T[9];
            acc2 += (d4 * d4 + d9 * d9) * noobjf;

            float m = -1e30f;
            #pragma unroll
            for (int c = 0; c < 20; c++) m = fmaxf(m, P[10 + c]);
            float sum = 0.0f;
            #pragma unroll
            for (int c = 0; c < 20; c++) sum += __expf(P[10 + c] - m);
            float tm = -1e30f; int targc = 0;
            #pragma unroll
            for (int c = 0; c < 20; c++) {
                float v = T[10 + c];
                if (v > tm) { tm = v; targc = c; }  // first-occurrence argmax
            }
            float ce = m + __logf(sum) - P[10 + targc];
            acc3 += ce * objf;
            acc4 += objf;
        }
        __syncthreads();
    }

    // ---- deterministic in-block reduction ----
    __shared__ float sred[5][TPB / 32];
    const unsigned mask = 0xffffffffu;
    #pragma unroll
    for (int off = 16; off; off >>= 1) {
        acc0 += __shfl_down_sync(mask, acc0, off);
        acc1 += __shfl_down_sync(mask, acc1, off);
        acc2 += __shfl_down_sync(mask, acc2, off);
        acc3 += __shfl_down_sync(mask, acc3, off);
        acc4 += __shfl_down_sync(mask, acc4, off);
    }
    int lane = tid & 31, w = tid >> 5;
    if (lane == 0) {
        sred[0][w] = acc0; sred[1][w] = acc1; sred[2][w] = acc2;
        sred[3][w] = acc3; sred[4][w] = acc4;
    }
    __syncthreads();
    if (tid == 0) {
        float r0 = 0.f, r1 = 0.f, r2 = 0.f, r3 = 0.f, r4 = 0.f;
        #pragma unroll
        for (int i = 0; i < TPB / 32; i++) {
            r0 += sred[0][i]; r1 += sred[1][i]; r2 += sred[2][i];
            r3 += sred[3][i]; r4 += sred[4][i];
        }
        g_partials[blockIdx.x * 5 + 0] = r0;
        g_partials[blockIdx.x * 5 + 1] = r1;
        g_partials[blockIdx.x * 5 + 2] = r2;
        g_partials[blockIdx.x * 5 + 3] = r3;
        g_partials[blockIdx.x * 5 + 4] = r4;
    }

    // ---- ticket: last finishing block does the final reduction ----
    __shared__ int amLast;
    __threadfence();
    __syncthreads();
    if (tid == 0) {
        unsigned tk = atomicAdd(&g_ticket, 1u);
        amLast = (tk == (unsigned)(nb - 1));
    }
    __syncthreads();

    if (amLast) {
        float a0 = 0.f, a1 = 0.f, a2 = 0.f, a3 = 0.f, a4 = 0.f;
        for (int j = tid; j < nb; j += TPB) {
            a0 += g_partials[j * 5 + 0];
            a1 += g_partials[j * 5 + 1];
            a2 += g_partials[j * 5 + 2];
            a3 += g_partials[j * 5 + 3];
            a4 += g_partials[j * 5 + 4];
        }
        #pragma unroll
        for (int off = 16; off; off >>= 1) {
            a0 += __shfl_down_sync(mask, a0, off);
            a1 += __shfl_down_sync(mask, a1, off);
            a2 += __shfl_down_sync(mask, a2, off);
            a3 += __shfl_down_sync(mask, a3, off);
            a4 += __shfl_down_sync(mask, a4, off);
        }
        if (lane == 0) {
            sred[0][w] = a0; sred[1][w] = a1; sred[2][w] = a2;
            sred[3][w] = a3; sred[4][w] = a4;
        }
        __syncthreads();
        if (tid == 0) {
            float loc = 0.f, cobj = 0.f, cno = 0.f, ce = 0.f, nobj = 0.f;
            #pragma unroll
            for (int i = 0; i < TPB / 32; i++) {
                loc += sred[0][i]; cobj += sred[1][i]; cno += sred[2][i];
                ce  += sred[3][i]; nobj += sred[4][i];
            }
            float n   = fmaxf(nobj, 1.0f);
            float cls = ce / n;
            out[0] = (5.0f * loc + cobj + 0.5f * cno + cls) * invB;
            out[1] = loc;
            out[2] = cobj;
            out[3] = cno;
            out[4] = cls;
            __threadfence();
            g_ticket = 0;   // reset for next graph replay (deterministic)
        }
    }
}

extern "C" void kernel_launch(void* const* d_in, const int* in_sizes, int n_in,
                              void* d_out, int out_size)
{
    const float* pred   = (const float*)d_in[0];
    const float* target = (const float*)d_in[1];
    int n_elems = in_sizes[0];
    int n_cells = n_elems / 30;

    static bool configured = false;
    if (!configured) {
        cudaFuncSetAttribute(yolo_fused_kernel,
                             cudaFuncAttributeMaxDynamicSharedMemorySize,
                             SMEM_BYTES);
        configured = true;
    }

    int ntiles = (n_cells + TILE - 1) / TILE;
    int grid = 444;                       // 148 SMs x 3 CTAs (61.4 KB smem each)
    if (grid > ntiles) grid = ntiles;
    if (grid < 1) grid = 1;
    if (grid > GRID_MAX) grid = GRID_MAX;

    float invB = 49.0f / (float)n_cells;  // B = n_cells / 49

    yolo_fused_kernel<<<grid, TPB, SMEM_BYTES>>>(pred, target, n_cells, invB,
                                                 (float*)d_out);
}

// round 17
// speedup vs baseline: 1.0922x; 1.0375x over previous
#include <cuda_runtime.h>
#include <cstdint>

// YOLOv1 loss — single fused kernel, cp.async 2-stage pipeline, ticket finalize.
// R17 = confirmed 38.8us winner + L2::256B fetch-granularity promotion on the
// hot-path cp.async (every byte of both tensors is consumed -> zero waste).

#define TPB   128
#define TILE  128
#define NF4   (TILE * 30 / 4)          // 960 float4 per tensor per tile
#define STAGE_BYTES (2 * NF4 * 16)     // pred+target, one stage = 30720 B
#define SMEM_BYTES  (2 * STAGE_BYTES)  // 2 stages = 61440 B
#define GRID_MAX 1024

__device__ float g_partials[GRID_MAX * 5];
__device__ unsigned int g_ticket = 0;

// 16B async copy with 256B L2 fetch promotion.
__device__ __forceinline__ void cp16(unsigned dst, const void* src) {
    asm volatile("cp.async.cg.shared.global.L2::256B [%0], [%1], 16;"
                 :: "r"(dst), "l"(src));
}

__device__ __forceinline__ float iou_fn(float bx, float by, float bw, float bh,
                                        float tx, float ty, float tw, float th)
{
    float ax1 = bx - bw * 0.5f, ay1 = by - bh * 0.5f;
    float ax2 = bx + bw * 0.5f, ay2 = by + bh * 0.5f;
    float cx1 = tx - tw * 0.5f, cy1 = ty - th * 0.5f;
    float cx2 = tx + tw * 0.5f, cy2 = ty + th * 0.5f;
    float iw = fmaxf(fminf(ax2, cx2) - fmaxf(ax1, cx1), 0.0f);
    float ih = fmaxf(fminf(ay2, cy2) - fmaxf(ay1, cy1), 0.0f);
    float inter = iw * ih;
    float uni = bw * bh + tw * th - inter;
    return inter / fmaxf(uni, 1e-10f);
}

extern __shared__ float4 dynbuf[];   // [2 stages][2 tensors][NF4]

__global__ __launch_bounds__(TPB)
void yolo_fused_kernel(const float* __restrict__ pred,
                       const float* __restrict__ target,
                       int n_cells, float invB,
                       float* __restrict__ out)
{
    const int tid = threadIdx.x;
    const int nb  = gridDim.x;
    const int ntiles = (n_cells + TILE - 1) / TILE;

    float acc0 = 0.f, acc1 = 0.f, acc2 = 0.f, acc3 = 0.f, acc4 = 0.f;

    // ---- issue loads for one tile into stage s (one commit_group per call) ----
    auto issue = [&](int tile, int s) {
        long long c0 = (long long)tile * TILE;
        int valid = (int)min((long long)TILE, (long long)n_cells - c0);
        const float* pg = pred   + c0 * 30;
        const float* tg = target + c0 * 30;
        float* sp = (float*)(dynbuf + (size_t)s * 2 * NF4);
        float* st = sp + NF4 * 4;
        if (valid == TILE) {
            unsigned bp = (unsigned)__cvta_generic_to_shared(sp);
            unsigned bt = (unsigned)__cvta_generic_to_shared(st);
            #pragma unroll 4
            for (int i = tid; i < NF4; i += TPB) {
                cp16(bp + 16u * i, ((const float4*)pg) + i);
                cp16(bt + 16u * i, ((const float4*)tg) + i);
            }
        } else {
            for (int i = tid; i < valid * 30; i += TPB) {
                sp[i] = pg[i];
                st[i] = tg[i];
            }
        }
        asm volatile("cp.async.commit_group;");
    };

    int t = blockIdx.x;
    if (t < ntiles) issue(t, 0);

    int s = 0;
    for (; t < ntiles; t += nb, s ^= 1) {
        long long c0 = (long long)t * TILE;
        int valid = (int)min((long long)TILE, (long long)n_cells - c0);

        int tn = t + nb;
        if (tn < ntiles) {
            issue(tn, s ^ 1);
            asm volatile("cp.async.wait_group 1;");
        } else {
            asm volatile("cp.async.wait_group 0;");
        }
        __syncthreads();

        if (tid < valid) {
            const float* sp = (const float*)(dynbuf + (size_t)s * 2 * NF4);
            const float* P = sp + tid * 30;
            const float* T = sp + NF4 * 4 + tid * 30;

            float t4v  = T[4];
            float objf = (t4v == 1.0f) ? 1.0f : 0.0f;
            float noobjf = 1.0f - objf;

            float tx = T[0], ty = T[1], tw = T[2], th = T[3];
            float i0 = iou_fn(P[0], P[1], P[2], P[3], tx, ty, tw, th);
            float i1 = iou_fn(P[5], P[6], P[7], P[8], tx, ty, tw, th);

            bool b0 = (i0 > i1);   // ties -> box 1 (matches jnp.where)
            float wx = b0 ? P[0] : P[5];
            float wy = b0 ? P[1] : P[6];
            float ww = b0 ? P[2] : P[7];
            float wh = b0 ? P[3] : P[8];
            float wc = b0 ? P[4] : P[9];
            float wiou = fmaxf(i0, i1);

            float dx = wx - tx, dy = wy - ty;
            float dw = sqrtf(ww) - sqrtf(tw);
            float dh = sqrtf(wh) - sqrtf(th);
            acc0 += (dx * dx + dy * dy + dw * dw + dh * dh) * objf;

            float dc = wc - wiou;
            acc1 += dc * dc * objf;

            float d4 = P[4] - t4v;
            float d9 = P[9] - T[9];
            acc2 += (d4 * d4 + d9 * d9) * noobjf;

            float m = -1e30f;
            #pragma unroll
            for (int c = 0; c < 20; c++) m = fmaxf(m, P[10 + c]);
            float sum = 0.0f;
            #pragma unroll
            for (int c = 0; c < 20; c++) sum += __expf(P[10 + c] - m);
            float tm = -1e30f; int targc = 0;
            #pragma unroll
            for (int c = 0; c < 20; c++) {
                float v = T[10 + c];
                if (v > tm) { tm = v; targc = c; }  // first-occurrence argmax
            }
            float ce = m + __logf(sum) - P[10 + targc];
            acc3 += ce * objf;
            acc4 += objf;
        }
        __syncthreads();
    }

    // ---- deterministic in-block reduction ----
    __shared__ float sred[5][TPB / 32];
    const unsigned mask = 0xffffffffu;
    #pragma unroll
    for (int off = 16; off; off >>= 1) {
        acc0 += __shfl_down_sync(mask, acc0, off);
        acc1 += __shfl_down_sync(mask, acc1, off);
        acc2 += __shfl_down_sync(mask, acc2, off);
        acc3 += __shfl_down_sync(mask, acc3, off);
        acc4 += __shfl_down_sync(mask, acc4, off);
    }
    int lane = tid & 31, w = tid >> 5;
    if (lane == 0) {
        sred[0][w] = acc0; sred[1][w] = acc1; sred[2][w] = acc2;
        sred[3][w] = acc3; sred[4][w] = acc4;
    }
    __syncthreads();
    if (tid == 0) {
        float r0 = 0.f, r1 = 0.f, r2 = 0.f, r3 = 0.f, r4 = 0.f;
        #pragma unroll
        for (int i = 0; i < TPB / 32; i++) {
            r0 += sred[0][i]; r1 += sred[1][i]; r2 += sred[2][i];
            r3 += sred[3][i]; r4 += sred[4][i];
        }
        g_partials[blockIdx.x * 5 + 0] = r0;
        g_partials[blockIdx.x * 5 + 1] = r1;
        g_partials[blockIdx.x * 5 + 2] = r2;
        g_partials[blockIdx.x * 5 + 3] = r3;
        g_partials[blockIdx.x * 5 + 4] = r4;
    }

    // ---- ticket: last finishing block does the final reduction ----
    __shared__ int amLast;
    __threadfence();
    __syncthreads();
    if (tid == 0) {
        unsigned tk = atomicAdd(&g_ticket, 1u);
        amLast = (tk == (unsigned)(nb - 1));
    }
    __syncthreads();

    if (amLast) {
        float a0 = 0.f, a1 = 0.f, a2 = 0.f, a3 = 0.f, a4 = 0.f;
        for (int j = tid; j < nb; j += TPB) {
            a0 += g_partials[j * 5 + 0];
            a1 += g_partials[j * 5 + 1];
            a2 += g_partials[j * 5 + 2];
            a3 += g_partials[j * 5 + 3];
            a4 += g_partials[j * 5 + 4];
        }
        #pragma unroll
        for (int off = 16; off; off >>= 1) {
            a0 += __shfl_down_sync(mask, a0, off);
            a1 += __shfl_down_sync(mask, a1, off);
            a2 += __shfl_down_sync(mask, a2, off);
            a3 += __shfl_down_sync(mask, a3, off);
            a4 += __shfl_down_sync(mask, a4, off);
        }
        if (lane == 0) {
            sred[0][w] = a0; sred[1][w] = a1; sred[2][w] = a2;
            sred[3][w] = a3; sred[4][w] = a4;
        }
        __syncthreads();
        if (tid == 0) {
            float loc = 0.f, cobj = 0.f, cno = 0.f, ce = 0.f, nobj = 0.f;
            #pragma unroll
            for (int i = 0; i < TPB / 32; i++) {
                loc += sred[0][i]; cobj += sred[1][i]; cno += sred[2][i];
                ce  += sred[3][i]; nobj += sred[4][i];
            }
            float n   = fmaxf(nobj, 1.0f);
            float cls = ce / n;
            out[0] = (5.0f * loc + cobj + 0.5f * cno + cls) * invB;
            out[1] = loc;
            out[2] = cobj;
            out[3] = cno;
            out[4] = cls;
            __threadfence();
            g_ticket = 0;   // reset for next graph replay (deterministic)
        }
    }
}

extern "C" void kernel_launch(void* const* d_in, const int* in_sizes, int n_in,
                              void* d_out, int out_size)
{
    const float* pred   = (const float*)d_in[0];
    const float* target = (const float*)d_in[1];
    int n_elems = in_sizes[0];
    int n_cells = n_elems / 30;

    static bool configured = false;
    if (!configured) {
        cudaFuncSetAttribute(yolo_fused_kernel,
                             cudaFuncAttributeMaxDynamicSharedMemorySize,
                             SMEM_BYTES);
        configured = true;
    }

    int ntiles = (n_cells + TILE - 1) / TILE;
    int grid = 444;                       // 148 SMs x 3 CTAs (61.4 KB smem each)
    if (grid > ntiles) grid = ntiles;
    if (grid < 1) grid = 1;
    if (grid > GRID_MAX) grid = GRID_MAX;

    float invB = 49.0f / (float)n_cells;  // B = n_cells / 49

    yolo_fused_kernel<<<grid, TPB, SMEM_BYTES>>>(pred, target, n_cells, invB,
                                                 (float*)d_out);
}